// round 15
// baseline (speedup 1.0000x reference)
#include <cuda_runtime.h>
#include <cuda_fp16.h>
#include <math.h>

// Problem constants
#define BATCH 4
#define SEQ   4096
#define EMB   1024
#define HEAD  64
#define ROWS  (BATCH * SEQ)          // 16384
#define NQT   (SEQ / 64)             // 64 query tiles per batch
#define SCALE 0.03125f               // 1/sqrt(1024)
#define SCALE_LOG2E 0.045098157f     // SCALE * log2(e)

// Scratch: q,k as fp16 [row][64]; v TRANSPOSED fp16 [b][h][T]
__device__ __half g_qh[(size_t)ROWS * HEAD];
__device__ __half g_kh[(size_t)ROWS * HEAD];
__device__ __half g_vt[(size_t)BATCH * HEAD * SEQ];

__device__ __forceinline__ float ex2(float x) {
    float y;
    asm("ex2.approx.ftz.f32 %0, %1;" : "=f"(y) : "f"(x));
    return y;
}
__device__ __forceinline__ float tf32(float v) {
    unsigned t;
    asm("cvt.rna.tf32.f32 %0, %1;" : "=r"(t) : "f"(v));
    return __uint_as_float(t);
}
__device__ __forceinline__ void mma_tf32(float d[4],
                                         unsigned a0, unsigned a1,
                                         unsigned a2, unsigned a3,
                                         unsigned b0, unsigned b1) {
    asm("mma.sync.aligned.m16n8k8.row.col.f32.tf32.tf32.f32 "
        "{%0,%1,%2,%3}, {%4,%5,%6,%7}, {%8,%9}, {%0,%1,%2,%3};"
        : "+f"(d[0]), "+f"(d[1]), "+f"(d[2]), "+f"(d[3])
        : "r"(a0), "r"(a1), "r"(a2), "r"(a3), "r"(b0), "r"(b1));
}
__device__ __forceinline__ void mma_f16(float d[4],
                                        unsigned a0, unsigned a1,
                                        unsigned a2, unsigned a3,
                                        unsigned b0, unsigned b1) {
    asm("mma.sync.aligned.m16n8k16.row.col.f32.f16.f16.f32 "
        "{%0,%1,%2,%3}, {%4,%5,%6,%7}, {%8,%9}, {%0,%1,%2,%3};"
        : "+f"(d[0]), "+f"(d[1]), "+f"(d[2]), "+f"(d[3])
        : "r"(a0), "r"(a1), "r"(a2), "r"(a3), "r"(b0), "r"(b1));
}
__device__ __forceinline__ void cpasync16(unsigned dst, const void* src) {
    asm volatile("cp.async.cg.shared.global [%0], [%1], 16;"
                 :: "r"(dst), "l"(src));
}
__device__ __forceinline__ unsigned ldh32(const __half* p) {
    return *(const unsigned*)p;
}

// ---------------------------------------------------------------------------
// Kernel 1: qkv projection via tf32 mma.sync; epilogue emits fp16
// (q,k natural layout; v transposed to [b][h][T]).
// ---------------------------------------------------------------------------
__global__ __launch_bounds__(256) void qkv_mma_kernel(
    const float* __restrict__ x,
    const float* __restrict__ Wq,
    const float* __restrict__ Wk,
    const float* __restrict__ Wv)
{
    __shared__ float As[128][36];
    __shared__ float Bs[32][200];

    const int tid  = threadIdx.x;
    const int lane = tid & 31;
    const int wid  = tid >> 5;
    const int wm   = wid & 3;
    const int wn   = wid >> 2;
    const int rowBase = blockIdx.x * 128;
    const int row4 = lane >> 2;
    const int col4 = lane & 3;

    float acc[2][12][4];
#pragma unroll
    for (int mt = 0; mt < 2; mt++)
#pragma unroll
        for (int nt = 0; nt < 12; nt++)
#pragma unroll
            for (int e = 0; e < 4; e++) acc[mt][nt][e] = 0.0f;

    for (int kc = 0; kc < EMB; kc += 32) {
#pragma unroll
        for (int u = 0; u < 4; u++) {
            int s  = tid + 256 * u;
            int r  = s >> 3;
            int c4 = (s & 7) * 4;
            float4 vx = *(const float4*)&x[(size_t)(rowBase + r) * EMB + kc + c4];
            As[r][c4 + 0] = tf32(vx.x);
            As[r][c4 + 1] = tf32(vx.y);
            As[r][c4 + 2] = tf32(vx.z);
            As[r][c4 + 3] = tf32(vx.w);
        }
#pragma unroll
        for (int u = 0; u < 6; u++) {
            int s   = tid + 256 * u;
            int k   = s / 48;
            int rem = s % 48;
            int m   = rem >> 4;
            int c4  = (rem & 15) * 4;
            const float* __restrict__ W = (m == 0) ? Wq : (m == 1) ? Wk : Wv;
            float4 w = *(const float4*)&W[(size_t)(kc + k) * HEAD + c4];
            Bs[k][m * 64 + c4 + 0] = tf32(w.x);
            Bs[k][m * 64 + c4 + 1] = tf32(w.y);
            Bs[k][m * 64 + c4 + 2] = tf32(w.z);
            Bs[k][m * 64 + c4 + 3] = tf32(w.w);
        }
        __syncthreads();

#pragma unroll
        for (int ks = 0; ks < 4; ks++) {
            const int kk = ks * 8;
            unsigned a[2][4];
#pragma unroll
            for (int mt = 0; mt < 2; mt++) {
                int m0 = wm * 32 + mt * 16;
                a[mt][0] = __float_as_uint(As[m0 + row4][kk + col4]);
                a[mt][1] = __float_as_uint(As[m0 + row4 + 8][kk + col4]);
                a[mt][2] = __float_as_uint(As[m0 + row4][kk + col4 + 4]);
                a[mt][3] = __float_as_uint(As[m0 + row4 + 8][kk + col4 + 4]);
            }
#pragma unroll
            for (int nt = 0; nt < 12; nt++) {
                int n0 = wn * 96 + nt * 8;
                unsigned b0 = __float_as_uint(Bs[kk + col4][n0 + row4]);
                unsigned b1 = __float_as_uint(Bs[kk + col4 + 4][n0 + row4]);
                mma_tf32(acc[0][nt], a[0][0], a[0][1], a[0][2], a[0][3], b0, b1);
                mma_tf32(acc[1][nt], a[1][0], a[1][1], a[1][2], a[1][3], b0, b1);
            }
        }
        __syncthreads();
    }

    // Epilogue: emit fp16. q,k natural; v transposed to g_vt[b][h][T].
#pragma unroll
    for (int mt = 0; mt < 2; mt++) {
#pragma unroll
        for (int nt = 0; nt < 12; nt++) {
            int n0 = wn * 96 + nt * 8 + 2 * col4;
            int m  = n0 >> 6;
            int nc = n0 & 63;
            int r  = rowBase + wm * 32 + mt * 16 + row4;
            if (m < 2) {
                __half* outm = (m == 0) ? g_qh : g_kh;
                *(__half2*)&outm[(size_t)r * HEAD + nc] =
                    __floats2half2_rn(acc[mt][nt][0], acc[mt][nt][1]);
                *(__half2*)&outm[(size_t)(r + 8) * HEAD + nc] =
                    __floats2half2_rn(acc[mt][nt][2], acc[mt][nt][3]);
            } else {
                int bb = r >> 12;
                int t  = r & 4095;
                g_vt[((size_t)(bb * 64 + nc))     * SEQ + t]     = __float2half(acc[mt][nt][0]);
                g_vt[((size_t)(bb * 64 + nc + 1)) * SEQ + t]     = __float2half(acc[mt][nt][1]);
                g_vt[((size_t)(bb * 64 + nc))     * SEQ + t + 8] = __float2half(acc[mt][nt][2]);
                g_vt[((size_t)(bb * 64 + nc + 1)) * SEQ + t + 8] = __float2half(acc[mt][nt][3]);
            }
        }
    }
}

// ---------------------------------------------------------------------------
// Kernel 2: causal flash attention, fp16 m16n8k16 mma.sync, cp.async
// double-buffered K/Vt. grid = (NQT/2, BATCH), block = 512 (two halves).
// All smem tiles 64 rows x 72 halfs (36 words: bank = 4*row4+col4, clean).
// Per half: Qs + Pt + 2*Ks + 2*Vt = 6 * 4608 halfs = 55296 B.
// ---------------------------------------------------------------------------
#define ST_H 72
#define TILE_H (64 * ST_H)                    // 4608 halfs
#define HALF_HALFS (6 * TILE_H)               // 27648 halfs per half-block

__global__ __launch_bounds__(512) void attn_kernel(float* __restrict__ out)
{
    extern __shared__ __half smh[];
    const int half_id = threadIdx.x >> 8;
    const int tid  = threadIdx.x & 255;
    const int barid = half_id + 1;

    __half* Qs  = smh + half_id * HALF_HALFS;  // [q][d]
    __half* Pt  = Qs + TILE_H;                 // [q][key]
    __half* Ks0 = Pt + TILE_H;                 // [key][d]
    __half* Ks1 = Ks0 + TILE_H;
    __half* Vt0 = Ks1 + TILE_H;                // [h][key]
    __half* Vt1 = Vt0 + TILE_H;

    const int b  = blockIdx.y;
    const int p  = blockIdx.x;
    const int qt = half_id ? p : (NQT - 1 - p);
    const int qbase = qt * 64;

    const __half* __restrict__ qg = g_qh + (size_t)b * SEQ * HEAD;
    const __half* __restrict__ kg = g_kh + (size_t)b * SEQ * HEAD;
    const __half* __restrict__ vt = g_vt + (size_t)b * HEAD * SEQ;

    const int lane = tid & 31;
    const int hwid = tid >> 5;
    const int wm   = hwid & 1;
    const int wn   = hwid >> 1;
    const int row4 = lane >> 2;
    const int col4 = lane & 3;
    const int m0   = wm * 32;
    const int n0   = wn * 16;

    // Staging: 64 rows x 8 chunks of 16B (8 halfs); 512 chunks, 2 per thread
    const int srow[2] = { tid >> 3, (tid + 256) >> 3 };
    const int sch8    = (tid & 7) * 8;

#define BSYNC() asm volatile("bar.sync %0, 256;" :: "r"(barid) : "memory")

    // Prologue: async-load Q + K/Vt tile 0
    {
        unsigned qsm = (unsigned)__cvta_generic_to_shared(Qs);
        unsigned ksm = (unsigned)__cvta_generic_to_shared(Ks0);
        unsigned vsm = (unsigned)__cvta_generic_to_shared(Vt0);
#pragma unroll
        for (int u = 0; u < 2; u++) {
            cpasync16(qsm + (srow[u] * ST_H + sch8) * 2,
                      &qg[(size_t)(qbase + srow[u]) * HEAD + sch8]);
            cpasync16(ksm + (srow[u] * ST_H + sch8) * 2,
                      &kg[(size_t)srow[u] * HEAD + sch8]);
            cpasync16(vsm + (srow[u] * ST_H + sch8) * 2,
                      &vt[(size_t)srow[u] * SEQ + sch8]);
        }
        asm volatile("cp.async.commit_group;");
        asm volatile("cp.async.wait_group 0;");
    }
    BSYNC();

    // Hoist Q A-fragments: [mt][k16 step][4]
    unsigned qa[2][4][4];
#pragma unroll
    for (int mt = 0; mt < 2; mt++) {
        const int rlo = m0 + mt * 16 + row4;
#pragma unroll
        for (int k4 = 0; k4 < 4; k4++) {
            const int kk = k4 * 16;
            qa[mt][k4][0] = ldh32(&Qs[rlo * ST_H + kk + 2 * col4]);
            qa[mt][k4][1] = ldh32(&Qs[(rlo + 8) * ST_H + kk + 2 * col4]);
            qa[mt][k4][2] = ldh32(&Qs[rlo * ST_H + kk + 2 * col4 + 8]);
            qa[mt][k4][3] = ldh32(&Qs[(rlo + 8) * ST_H + kk + 2 * col4 + 8]);
        }
    }

    float of[2][2][4];
    float lsum[2][2];
#pragma unroll
    for (int mt = 0; mt < 2; mt++) {
        lsum[mt][0] = 0.0f; lsum[mt][1] = 0.0f;
#pragma unroll
        for (int nt = 0; nt < 2; nt++)
#pragma unroll
            for (int e = 0; e < 4; e++) of[mt][nt][e] = 0.0f;
    }

    for (int jt = 0; jt <= qt; jt++) {
        __half* Ks = (jt & 1) ? Ks1 : Ks0;
        __half* Vs = (jt & 1) ? Vt1 : Vt0;

        if (jt > 0) asm volatile("cp.async.wait_group 0;");
        BSYNC();

        // Issue async load of tile jt+1
        if (jt < qt) {
            const int nb = (jt + 1) * 64;
            __half* Ksn = (jt & 1) ? Ks0 : Ks1;
            __half* Vsn = (jt & 1) ? Vt0 : Vt1;
            unsigned ksm = (unsigned)__cvta_generic_to_shared(Ksn);
            unsigned vsm = (unsigned)__cvta_generic_to_shared(Vsn);
#pragma unroll
            for (int u = 0; u < 2; u++) {
                cpasync16(ksm + (srow[u] * ST_H + sch8) * 2,
                          &kg[(size_t)(nb + srow[u]) * HEAD + sch8]);
                cpasync16(vsm + (srow[u] * ST_H + sch8) * 2,
                          &vt[(size_t)srow[u] * SEQ + nb + sch8]);
            }
            asm volatile("cp.async.commit_group;");
        }

        // S = Q K^T  (fp16 k16; A from registers, B from Ks rows)
        float sf[2][2][4];
#pragma unroll
        for (int mt = 0; mt < 2; mt++)
#pragma unroll
            for (int nt = 0; nt < 2; nt++)
#pragma unroll
                for (int e = 0; e < 4; e++) sf[mt][nt][e] = 0.0f;

#pragma unroll
        for (int k4 = 0; k4 < 4; k4++) {
            const int kk = k4 * 16;
#pragma unroll
            for (int nt = 0; nt < 2; nt++) {
                const int nr = n0 + nt * 8 + row4;
                unsigned b0 = ldh32(&Ks[nr * ST_H + kk + 2 * col4]);
                unsigned b1 = ldh32(&Ks[nr * ST_H + kk + 2 * col4 + 8]);
                mma_f16(sf[0][nt], qa[0][k4][0], qa[0][k4][1], qa[0][k4][2], qa[0][k4][3], b0, b1);
                mma_f16(sf[1][nt], qa[1][k4][0], qa[1][k4][1], qa[1][k4][2], qa[1][k4][3], b0, b1);
            }
        }

        // p = exp(S*scale), mask diagonal, store fp16 Pt, accumulate row sums
        const bool diag = (jt == qt);
#pragma unroll
        for (int mt = 0; mt < 2; mt++) {
            const int rlo = m0 + mt * 16 + row4;
            const int rhi = rlo + 8;
#pragma unroll
            for (int nt = 0; nt < 2; nt++) {
                const int cb = n0 + nt * 8 + 2 * col4;
                float p0 = ex2(sf[mt][nt][0] * SCALE_LOG2E);
                float p1 = ex2(sf[mt][nt][1] * SCALE_LOG2E);
                float p2 = ex2(sf[mt][nt][2] * SCALE_LOG2E);
                float p3 = ex2(sf[mt][nt][3] * SCALE_LOG2E);
                if (diag) {
                    if (cb     > rlo) p0 = 0.0f;
                    if (cb + 1 > rlo) p1 = 0.0f;
                    if (cb     > rhi) p2 = 0.0f;
                    if (cb + 1 > rhi) p3 = 0.0f;
                }
                __half2 h01 = __floats2half2_rn(p0, p1);
                __half2 h23 = __floats2half2_rn(p2, p3);
                *(__half2*)&Pt[rlo * ST_H + cb] = h01;
                *(__half2*)&Pt[rhi * ST_H + cb] = h23;
                float2 f01 = __half22float2(h01);
                float2 f23 = __half22float2(h23);
                lsum[mt][0] += f01.x + f01.y;
                lsum[mt][1] += f23.x + f23.y;
            }
        }
        BSYNC();   // Pt fully written

        // O += P V  (A from Pt rows, B from Vt rows)
#pragma unroll
        for (int k4 = 0; k4 < 4; k4++) {
            const int kk = k4 * 16;
            unsigned a[2][4];
#pragma unroll
            for (int mt = 0; mt < 2; mt++) {
                const int rlo = m0 + mt * 16 + row4;
                a[mt][0] = ldh32(&Pt[rlo * ST_H + kk + 2 * col4]);
                a[mt][1] = ldh32(&Pt[(rlo + 8) * ST_H + kk + 2 * col4]);
                a[mt][2] = ldh32(&Pt[rlo * ST_H + kk + 2 * col4 + 8]);
                a[mt][3] = ldh32(&Pt[(rlo + 8) * ST_H + kk + 2 * col4 + 8]);
            }
#pragma unroll
            for (int nt = 0; nt < 2; nt++) {
                const int nr = n0 + nt * 8 + row4;
                unsigned b0 = ldh32(&Vs[nr * ST_H + kk + 2 * col4]);
                unsigned b1 = ldh32(&Vs[nr * ST_H + kk + 2 * col4 + 8]);
                mma_f16(of[0][nt], a[0][0], a[0][1], a[0][2], a[0][3], b0, b1);
                mma_f16(of[1][nt], a[1][0], a[1][1], a[1][2], a[1][3], b0, b1);
            }
        }
    }

    // Epilogue: reduce lsum; reuse Pt region as float scratch
    float* red = (float*)Pt;
#pragma unroll
    for (int mt = 0; mt < 2; mt++)
#pragma unroll
        for (int h = 0; h < 2; h++) {
            float v0 = lsum[mt][h];
            v0 += __shfl_xor_sync(0xffffffffu, v0, 1);
            v0 += __shfl_xor_sync(0xffffffffu, v0, 2);
            lsum[mt][h] = v0;
        }
    BSYNC();
    if (tid < 64) red[tid] = 0.0f;
    BSYNC();
    if (col4 == 0) {
#pragma unroll
        for (int mt = 0; mt < 2; mt++)
#pragma unroll
            for (int h = 0; h < 2; h++)
                atomicAdd(&red[m0 + mt * 16 + row4 + 8 * h], lsum[mt][h]);
    }
    BSYNC();

#pragma unroll
    for (int mt = 0; mt < 2; mt++) {
#pragma unroll
        for (int h = 0; h < 2; h++) {
            const int rl  = m0 + mt * 16 + row4 + 8 * h;
            const float inv = 1.0f / red[rl];
            const size_t R = (size_t)b * SEQ + qbase + rl;
#pragma unroll
            for (int nt = 0; nt < 2; nt++) {
                const int cb = n0 + nt * 8 + 2 * col4;
                *(float2*)&out[R * HEAD + cb] =
                    make_float2(of[mt][nt][2 * h] * inv, of[mt][nt][2 * h + 1] * inv);
            }
        }
    }
#undef BSYNC
}

// ---------------------------------------------------------------------------
extern "C" void kernel_launch(void* const* d_in, const int* in_sizes, int n_in,
                              void* d_out, int out_size)
{
    const float* x  = (const float*)d_in[0];
    const float* Wq = (const float*)d_in[1];
    const float* Wk = (const float*)d_in[2];
    const float* Wv = (const float*)d_in[3];
    float* out = (float*)d_out;

    // QKV projection on tensor cores (tf32 mma.sync, fp16 outputs)
    qkv_mma_kernel<<<ROWS / 128, 256>>>(x, Wq, Wk, Wv);

    // Paired-tile flash attention, fp16 mma, cp.async double-buffered
    {
        const int smem_bytes = 2 * HALF_HALFS * (int)sizeof(__half); // 110592
        static bool attr_set = false;
        if (!attr_set) {
            cudaFuncSetAttribute(attn_kernel,
                                 cudaFuncAttributeMaxDynamicSharedMemorySize,
                                 smem_bytes);
            attr_set = true;
        }
        dim3 grid(NQT / 2, BATCH);
        attn_kernel<<<grid, 512, smem_bytes>>>(out);
    }
}

// round 16
// speedup vs baseline: 1.6565x; 1.6565x over previous
#include <cuda_runtime.h>
#include <cuda_fp16.h>
#include <math.h>

// Problem constants
#define BATCH 4
#define SEQ   4096
#define EMB   1024
#define HEAD  64
#define ROWS  (BATCH * SEQ)          // 16384
#define NQT   (SEQ / 64)             // 64 query tiles per batch
#define SCALE 0.03125f               // 1/sqrt(1024)
#define SCALE_LOG2E 0.045098157f     // SCALE * log2(e)

// Scratch: q, k, v all fp16 natural [row][64]
__device__ __half g_qh[(size_t)ROWS * HEAD];
__device__ __half g_kh[(size_t)ROWS * HEAD];
__device__ __half g_vh[(size_t)ROWS * HEAD];

__device__ __forceinline__ float ex2(float x) {
    float y;
    asm("ex2.approx.ftz.f32 %0, %1;" : "=f"(y) : "f"(x));
    return y;
}
__device__ __forceinline__ float tf32(float v) {
    unsigned t;
    asm("cvt.rna.tf32.f32 %0, %1;" : "=r"(t) : "f"(v));
    return __uint_as_float(t);
}
__device__ __forceinline__ void mma_tf32(float d[4],
                                         unsigned a0, unsigned a1,
                                         unsigned a2, unsigned a3,
                                         unsigned b0, unsigned b1) {
    asm("mma.sync.aligned.m16n8k8.row.col.f32.tf32.tf32.f32 "
        "{%0,%1,%2,%3}, {%4,%5,%6,%7}, {%8,%9}, {%0,%1,%2,%3};"
        : "+f"(d[0]), "+f"(d[1]), "+f"(d[2]), "+f"(d[3])
        : "r"(a0), "r"(a1), "r"(a2), "r"(a3), "r"(b0), "r"(b1));
}
__device__ __forceinline__ void mma_f16(float d[4],
                                        unsigned a0, unsigned a1,
                                        unsigned a2, unsigned a3,
                                        unsigned b0, unsigned b1) {
    asm("mma.sync.aligned.m16n8k16.row.col.f32.f16.f16.f32 "
        "{%0,%1,%2,%3}, {%4,%5,%6,%7}, {%8,%9}, {%0,%1,%2,%3};"
        : "+f"(d[0]), "+f"(d[1]), "+f"(d[2]), "+f"(d[3])
        : "r"(a0), "r"(a1), "r"(a2), "r"(a3), "r"(b0), "r"(b1));
}
__device__ __forceinline__ void cpasync16(unsigned dst, const void* src) {
    asm volatile("cp.async.cg.shared.global [%0], [%1], 16;"
                 :: "r"(dst), "l"(src));
}
__device__ __forceinline__ unsigned ldh32(const __half* p) {
    return *(const unsigned*)p;
}

// ---------------------------------------------------------------------------
// Kernel 1: qkv projection via tf32 mma.sync; epilogue emits fp16, all three
// matrices in natural [row][64] layout (coalesced half2 writes).
// ---------------------------------------------------------------------------
__global__ __launch_bounds__(256) void qkv_mma_kernel(
    const float* __restrict__ x,
    const float* __restrict__ Wq,
    const float* __restrict__ Wk,
    const float* __restrict__ Wv)
{
    __shared__ float As[128][36];
    __shared__ float Bs[32][200];

    const int tid  = threadIdx.x;
    const int lane = tid & 31;
    const int wid  = tid >> 5;
    const int wm   = wid & 3;
    const int wn   = wid >> 2;
    const int rowBase = blockIdx.x * 128;
    const int row4 = lane >> 2;
    const int col4 = lane & 3;

    float acc[2][12][4];
#pragma unroll
    for (int mt = 0; mt < 2; mt++)
#pragma unroll
        for (int nt = 0; nt < 12; nt++)
#pragma unroll
            for (int e = 0; e < 4; e++) acc[mt][nt][e] = 0.0f;

    for (int kc = 0; kc < EMB; kc += 32) {
#pragma unroll
        for (int u = 0; u < 4; u++) {
            int s  = tid + 256 * u;
            int r  = s >> 3;
            int c4 = (s & 7) * 4;
            float4 vx = *(const float4*)&x[(size_t)(rowBase + r) * EMB + kc + c4];
            As[r][c4 + 0] = tf32(vx.x);
            As[r][c4 + 1] = tf32(vx.y);
            As[r][c4 + 2] = tf32(vx.z);
            As[r][c4 + 3] = tf32(vx.w);
        }
#pragma unroll
        for (int u = 0; u < 6; u++) {
            int s   = tid + 256 * u;
            int k   = s / 48;
            int rem = s % 48;
            int m   = rem >> 4;
            int c4  = (rem & 15) * 4;
            const float* __restrict__ W = (m == 0) ? Wq : (m == 1) ? Wk : Wv;
            float4 w = *(const float4*)&W[(size_t)(kc + k) * HEAD + c4];
            Bs[k][m * 64 + c4 + 0] = tf32(w.x);
            Bs[k][m * 64 + c4 + 1] = tf32(w.y);
            Bs[k][m * 64 + c4 + 2] = tf32(w.z);
            Bs[k][m * 64 + c4 + 3] = tf32(w.w);
        }
        __syncthreads();

#pragma unroll
        for (int ks = 0; ks < 4; ks++) {
            const int kk = ks * 8;
            unsigned a[2][4];
#pragma unroll
            for (int mt = 0; mt < 2; mt++) {
                int m0 = wm * 32 + mt * 16;
                a[mt][0] = __float_as_uint(As[m0 + row4][kk + col4]);
                a[mt][1] = __float_as_uint(As[m0 + row4 + 8][kk + col4]);
                a[mt][2] = __float_as_uint(As[m0 + row4][kk + col4 + 4]);
                a[mt][3] = __float_as_uint(As[m0 + row4 + 8][kk + col4 + 4]);
            }
#pragma unroll
            for (int nt = 0; nt < 12; nt++) {
                int n0 = wn * 96 + nt * 8;
                unsigned b0 = __float_as_uint(Bs[kk + col4][n0 + row4]);
                unsigned b1 = __float_as_uint(Bs[kk + col4 + 4][n0 + row4]);
                mma_tf32(acc[0][nt], a[0][0], a[0][1], a[0][2], a[0][3], b0, b1);
                mma_tf32(acc[1][nt], a[1][0], a[1][1], a[1][2], a[1][3], b0, b1);
            }
        }
        __syncthreads();
    }

    // Epilogue: emit fp16, natural layout for q, k, AND v.
#pragma unroll
    for (int mt = 0; mt < 2; mt++) {
#pragma unroll
        for (int nt = 0; nt < 12; nt++) {
            int n0 = wn * 96 + nt * 8 + 2 * col4;
            int m  = n0 >> 6;
            int nc = n0 & 63;
            int r  = rowBase + wm * 32 + mt * 16 + row4;
            __half* outm = (m == 0) ? g_qh : (m == 1) ? g_kh : g_vh;
            *(__half2*)&outm[(size_t)r * HEAD + nc] =
                __floats2half2_rn(acc[mt][nt][0], acc[mt][nt][1]);
            *(__half2*)&outm[(size_t)(r + 8) * HEAD + nc] =
                __floats2half2_rn(acc[mt][nt][2], acc[mt][nt][3]);
        }
    }
}

// ---------------------------------------------------------------------------
// Kernel 2: causal flash attention, fp16 m16n8k16 mma.sync, cp.async
// double-buffered K/V (both natural [row][64]); PV B-fragments via
// ldmatrix.x2.trans. grid = (NQT/2, BATCH), block = 512 (two halves).
// All smem tiles 64 rows x 72 halfs. Per half: 6 tiles = 55296 B.
// ---------------------------------------------------------------------------
#define ST_H 72
#define TILE_H (64 * ST_H)                    // 4608 halfs
#define HALF_HALFS (6 * TILE_H)               // 27648 halfs per half-block

__global__ __launch_bounds__(512) void attn_kernel(float* __restrict__ out)
{
    extern __shared__ __half smh[];
    const int half_id = threadIdx.x >> 8;
    const int tid  = threadIdx.x & 255;
    const int barid = half_id + 1;

    __half* Qs  = smh + half_id * HALF_HALFS;  // [q][d]
    __half* Pt  = Qs + TILE_H;                 // [q][key]
    __half* Ks0 = Pt + TILE_H;                 // [key][d]
    __half* Ks1 = Ks0 + TILE_H;
    __half* Vs0 = Ks1 + TILE_H;                // [key][h]  (natural!)
    __half* Vs1 = Vs0 + TILE_H;

    const int b  = blockIdx.y;
    const int p  = blockIdx.x;
    const int qt = half_id ? p : (NQT - 1 - p);
    const int qbase = qt * 64;

    const __half* __restrict__ qg = g_qh + (size_t)b * SEQ * HEAD;
    const __half* __restrict__ kg = g_kh + (size_t)b * SEQ * HEAD;
    const __half* __restrict__ vg = g_vh + (size_t)b * SEQ * HEAD;

    const int lane = tid & 31;
    const int hwid = tid >> 5;
    const int wm   = hwid & 1;
    const int wn   = hwid >> 1;
    const int row4 = lane >> 2;
    const int col4 = lane & 3;
    const int m0   = wm * 32;
    const int n0   = wn * 16;
    const int lrow = lane & 15;               // ldmatrix source row

    // Staging: 64 rows x 8 chunks of 16B; 512 chunks, 2 per thread
    const int srow[2] = { tid >> 3, (tid + 256) >> 3 };
    const int sch8    = (tid & 7) * 8;

#define BSYNC() asm volatile("bar.sync %0, 256;" :: "r"(barid) : "memory")

    // Prologue: async-load Q + K/V tile 0
    {
        unsigned qsm = (unsigned)__cvta_generic_to_shared(Qs);
        unsigned ksm = (unsigned)__cvta_generic_to_shared(Ks0);
        unsigned vsm = (unsigned)__cvta_generic_to_shared(Vs0);
#pragma unroll
        for (int u = 0; u < 2; u++) {
            cpasync16(qsm + (srow[u] * ST_H + sch8) * 2,
                      &qg[(size_t)(qbase + srow[u]) * HEAD + sch8]);
            cpasync16(ksm + (srow[u] * ST_H + sch8) * 2,
                      &kg[(size_t)srow[u] * HEAD + sch8]);
            cpasync16(vsm + (srow[u] * ST_H + sch8) * 2,
                      &vg[(size_t)srow[u] * HEAD + sch8]);
        }
        asm volatile("cp.async.commit_group;");
        asm volatile("cp.async.wait_group 0;");
    }
    BSYNC();

    // Hoist Q A-fragments: [mt][k16 step][4]
    unsigned qa[2][4][4];
#pragma unroll
    for (int mt = 0; mt < 2; mt++) {
        const int rlo = m0 + mt * 16 + row4;
#pragma unroll
        for (int k4 = 0; k4 < 4; k4++) {
            const int kk = k4 * 16;
            qa[mt][k4][0] = ldh32(&Qs[rlo * ST_H + kk + 2 * col4]);
            qa[mt][k4][1] = ldh32(&Qs[(rlo + 8) * ST_H + kk + 2 * col4]);
            qa[mt][k4][2] = ldh32(&Qs[rlo * ST_H + kk + 2 * col4 + 8]);
            qa[mt][k4][3] = ldh32(&Qs[(rlo + 8) * ST_H + kk + 2 * col4 + 8]);
        }
    }

    float of[2][2][4];
    float lsum[2][2];
#pragma unroll
    for (int mt = 0; mt < 2; mt++) {
        lsum[mt][0] = 0.0f; lsum[mt][1] = 0.0f;
#pragma unroll
        for (int nt = 0; nt < 2; nt++)
#pragma unroll
            for (int e = 0; e < 4; e++) of[mt][nt][e] = 0.0f;
    }

    for (int jt = 0; jt <= qt; jt++) {
        __half* Ks = (jt & 1) ? Ks1 : Ks0;
        __half* Vs = (jt & 1) ? Vs1 : Vs0;

        if (jt > 0) asm volatile("cp.async.wait_group 0;");
        BSYNC();

        // Issue async load of tile jt+1
        if (jt < qt) {
            const int nb = (jt + 1) * 64;
            __half* Ksn = (jt & 1) ? Ks0 : Ks1;
            __half* Vsn = (jt & 1) ? Vs0 : Vs1;
            unsigned ksm = (unsigned)__cvta_generic_to_shared(Ksn);
            unsigned vsm = (unsigned)__cvta_generic_to_shared(Vsn);
#pragma unroll
            for (int u = 0; u < 2; u++) {
                cpasync16(ksm + (srow[u] * ST_H + sch8) * 2,
                          &kg[(size_t)(nb + srow[u]) * HEAD + sch8]);
                cpasync16(vsm + (srow[u] * ST_H + sch8) * 2,
                          &vg[(size_t)(nb + srow[u]) * HEAD + sch8]);
            }
            asm volatile("cp.async.commit_group;");
        }

        // S = Q K^T  (fp16 k16; A from registers, B from Ks rows)
        float sf[2][2][4];
#pragma unroll
        for (int mt = 0; mt < 2; mt++)
#pragma unroll
            for (int nt = 0; nt < 2; nt++)
#pragma unroll
                for (int e = 0; e < 4; e++) sf[mt][nt][e] = 0.0f;

#pragma unroll
        for (int k4 = 0; k4 < 4; k4++) {
            const int kk = k4 * 16;
#pragma unroll
            for (int nt = 0; nt < 2; nt++) {
                const int nr = n0 + nt * 8 + row4;
                unsigned b0 = ldh32(&Ks[nr * ST_H + kk + 2 * col4]);
                unsigned b1 = ldh32(&Ks[nr * ST_H + kk + 2 * col4 + 8]);
                mma_f16(sf[0][nt], qa[0][k4][0], qa[0][k4][1], qa[0][k4][2], qa[0][k4][3], b0, b1);
                mma_f16(sf[1][nt], qa[1][k4][0], qa[1][k4][1], qa[1][k4][2], qa[1][k4][3], b0, b1);
            }
        }

        // p = exp(S*scale), mask diagonal, store fp16 Pt, accumulate row sums
        const bool diag = (jt == qt);
#pragma unroll
        for (int mt = 0; mt < 2; mt++) {
            const int rlo = m0 + mt * 16 + row4;
            const int rhi = rlo + 8;
#pragma unroll
            for (int nt = 0; nt < 2; nt++) {
                const int cb = n0 + nt * 8 + 2 * col4;
                float p0 = ex2(sf[mt][nt][0] * SCALE_LOG2E);
                float p1 = ex2(sf[mt][nt][1] * SCALE_LOG2E);
                float p2 = ex2(sf[mt][nt][2] * SCALE_LOG2E);
                float p3 = ex2(sf[mt][nt][3] * SCALE_LOG2E);
                if (diag) {
                    if (cb     > rlo) p0 = 0.0f;
                    if (cb + 1 > rlo) p1 = 0.0f;
                    if (cb     > rhi) p2 = 0.0f;
                    if (cb + 1 > rhi) p3 = 0.0f;
                }
                __half2 h01 = __floats2half2_rn(p0, p1);
                __half2 h23 = __floats2half2_rn(p2, p3);
                *(__half2*)&Pt[rlo * ST_H + cb] = h01;
                *(__half2*)&Pt[rhi * ST_H + cb] = h23;
                float2 f01 = __half22float2(h01);
                float2 f23 = __half22float2(h23);
                lsum[mt][0] += f01.x + f01.y;
                lsum[mt][1] += f23.x + f23.y;
            }
        }
        BSYNC();   // Pt fully written

        // O += P V  (A from Pt rows; B via ldmatrix.x2.trans on natural Vs)
        const unsigned vbase = (unsigned)__cvta_generic_to_shared(Vs);
#pragma unroll
        for (int k4 = 0; k4 < 4; k4++) {
            const int kk = k4 * 16;
            unsigned a[2][4];
#pragma unroll
            for (int mt = 0; mt < 2; mt++) {
                const int rlo = m0 + mt * 16 + row4;
                a[mt][0] = ldh32(&Pt[rlo * ST_H + kk + 2 * col4]);
                a[mt][1] = ldh32(&Pt[(rlo + 8) * ST_H + kk + 2 * col4]);
                a[mt][2] = ldh32(&Pt[rlo * ST_H + kk + 2 * col4 + 8]);
                a[mt][3] = ldh32(&Pt[(rlo + 8) * ST_H + kk + 2 * col4 + 8]);
            }
#pragma unroll
            for (int nt = 0; nt < 2; nt++) {
                unsigned b0, b1;
                unsigned addr = vbase + ((kk + lrow) * ST_H + n0 + nt * 8) * 2;
                asm volatile(
                    "ldmatrix.sync.aligned.m8n8.x2.trans.shared.b16 {%0,%1}, [%2];"
                    : "=r"(b0), "=r"(b1) : "r"(addr));
                mma_f16(of[0][nt], a[0][0], a[0][1], a[0][2], a[0][3], b0, b1);
                mma_f16(of[1][nt], a[1][0], a[1][1], a[1][2], a[1][3], b0, b1);
            }
        }
    }

    // Epilogue: reduce lsum; reuse Pt region as float scratch
    float* red = (float*)Pt;
#pragma unroll
    for (int mt = 0; mt < 2; mt++)
#pragma unroll
        for (int h = 0; h < 2; h++) {
            float v0 = lsum[mt][h];
            v0 += __shfl_xor_sync(0xffffffffu, v0, 1);
            v0 += __shfl_xor_sync(0xffffffffu, v0, 2);
            lsum[mt][h] = v0;
        }
    BSYNC();
    if (tid < 64) red[tid] = 0.0f;
    BSYNC();
    if (col4 == 0) {
#pragma unroll
        for (int mt = 0; mt < 2; mt++)
#pragma unroll
            for (int h = 0; h < 2; h++)
                atomicAdd(&red[m0 + mt * 16 + row4 + 8 * h], lsum[mt][h]);
    }
    BSYNC();

#pragma unroll
    for (int mt = 0; mt < 2; mt++) {
#pragma unroll
        for (int h = 0; h < 2; h++) {
            const int rl  = m0 + mt * 16 + row4 + 8 * h;
            const float inv = 1.0f / red[rl];
            const size_t R = (size_t)b * SEQ + qbase + rl;
#pragma unroll
            for (int nt = 0; nt < 2; nt++) {
                const int cb = n0 + nt * 8 + 2 * col4;
                *(float2*)&out[R * HEAD + cb] =
                    make_float2(of[mt][nt][2 * h] * inv, of[mt][nt][2 * h + 1] * inv);
            }
        }
    }
#undef BSYNC
}

// ---------------------------------------------------------------------------
extern "C" void kernel_launch(void* const* d_in, const int* in_sizes, int n_in,
                              void* d_out, int out_size)
{
    const float* x  = (const float*)d_in[0];
    const float* Wq = (const float*)d_in[1];
    const float* Wk = (const float*)d_in[2];
    const float* Wv = (const float*)d_in[3];
    float* out = (float*)d_out;

    // QKV projection on tensor cores (tf32 mma.sync, fp16 outputs)
    qkv_mma_kernel<<<ROWS / 128, 256>>>(x, Wq, Wk, Wv);

    // Paired-tile flash attention, fp16 mma, cp.async double-buffered
    {
        const int smem_bytes = 2 * HALF_HALFS * (int)sizeof(__half); // 110592
        static bool attr_set = false;
        if (!attr_set) {
            cudaFuncSetAttribute(attn_kernel,
                                 cudaFuncAttributeMaxDynamicSharedMemorySize,
                                 smem_bytes);
            attr_set = true;
        }
        dim3 grid(NQT / 2, BATCH);
        attn_kernel<<<grid, 512, smem_bytes>>>(out);
    }
}